// round 8
// baseline (speedup 1.0000x reference)
#include <cuda_runtime.h>
#include <math.h>

#define BB    2
#define NN    2048
#define EE    32768
#define FIN   256
#define NH    8
#define HID   8
#define F1    64
#define FOUT  64

#define NB    148
#define NT    1024
#define NWORDS (NN*NN/32)
#define MAXD  64      // per-warp staged edge capacity

// ---------------- scratch ------------------------------------------------------
__device__ float g_h1[BB * NN * F1];
__device__ float g_s1[BB * NN * NH];
__device__ float g_s2[BB * NN * NH];
__device__ float g_h2[BB * NN * FOUT];
__device__ float g_t1[BB * NN];
__device__ float g_t2[BB * NN];
__device__ int   g_cnt[NN];
__device__ int   g_offs[NN + 1];
__device__ int   g_tgt[EE];
__device__ unsigned g_bm[NWORDS];       // invariant: all-zero at launch entry
__device__ float g_mean1[BB * F1];      // invariant: zero at launch entry
__device__ float g_mean2[BB * FOUT];    // invariant: zero at launch entry
__device__ unsigned long long g_bar[8];

__device__ __forceinline__ void gridbar(int slot) {
    __threadfence();
    __syncthreads();
    if (threadIdx.x == 0) {
        unsigned long long old = atomicAdd(&g_bar[slot], 1ULL);
        unsigned long long target = (old / NB + 1ULL) * (unsigned long long)NB;
        volatile unsigned long long* p = (volatile unsigned long long*)&g_bar[slot];
        while (*p < target) { }
    }
    __syncthreads();
}

__device__ __forceinline__ float lrelu(float e) { return fmaxf(e, 0.2f * e); }

__global__ void __launch_bounds__(NT, 1) mega(
    const float* __restrict__ x,
    const int*   __restrict__ edges,
    const float* __restrict__ Wh,
    const float* __restrict__ ah,
    const float* __restrict__ bh,
    const float* __restrict__ Wo,
    const float* __restrict__ ao,
    const float* __restrict__ bo,
    float* __restrict__ out)
{
    const int tid = threadIdx.x;
    const int bid = blockIdx.x;

    __shared__ float sx[8192];        // 32KB multiplexed
    __shared__ float sred[1024];      // 4KB
    __shared__ int   stg[32][MAXD];   // 8KB per-warp staged targets

    // ===== P1: CSR build (block 147) || GEMM1 (blocks 0..127) =====
    if (bid == NB - 1) {
        int* scnt = (int*)sx;
        int* pps  = (int*)sred;
        for (int i = tid; i < NN; i += NT) scnt[i] = 0;
        __syncthreads();
        for (int i = tid; i < EE; i += NT) atomicAdd(&scnt[edges[i]], 1);
        __syncthreads();
        int a = scnt[2 * tid], b2 = scnt[2 * tid + 1];
        pps[tid] = a + b2;
        __syncthreads();
        for (int off = 1; off < NT; off <<= 1) {
            int v = pps[tid];
            int ad = (tid >= off) ? pps[tid - off] : 0;
            __syncthreads();
            pps[tid] = v + ad;
            __syncthreads();
        }
        int excl = pps[tid] - (a + b2);
        g_offs[2 * tid]     = excl;
        g_offs[2 * tid + 1] = excl + a;
        if (tid == NT - 1) g_offs[NN] = pps[tid];
        scnt[2 * tid]     = excl;
        scnt[2 * tid + 1] = excl + a;
        __syncthreads();
        for (int i = tid; i < EE; i += NT) {
            int s = edges[i], t = edges[EE + i];
            unsigned bit = (unsigned)s * NN + (unsigned)t;
            unsigned msk = 1u << (bit & 31u);
            unsigned old = atomicOr(&g_bm[bit >> 5], msk);
            if (!(old & msk)) {
                int slot = atomicAdd(&scnt[s], 1);
                g_tgt[slot] = t;
            }
        }
        __syncthreads();
        for (int n = tid; n < NN; n += NT) g_cnt[n] = scnt[n] - g_offs[n];
    } else if (bid < 128) {
        const int R = bid * 32;
        const int b = R >> 11;
        const float4* x4 = (const float4*)x + (size_t)R * (FIN / 4);
        float4* sx4 = (float4*)sx;
        for (int i = tid; i < 32 * (FIN / 4); i += NT) sx4[i] = x4[i];
        __syncthreads();
        const int j = tid & 63, rq = tid >> 6;
        const int h = j >> 3, o = j & 7;
        const float* w   = Wh + h * (FIN * HID) + o;
        const float* xr0 = sx + (rq * 2) * FIN;
        const float* xr1 = xr0 + FIN;
        float a0 = 0.f, a1 = 0.f, c0 = 0.f, c1 = 0.f;
#pragma unroll 8
        for (int f = 0; f < FIN; f += 2) {
            float w0 = __ldg(&w[f * HID]);
            float w1 = __ldg(&w[(f + 1) * HID]);
            a0 = fmaf(xr0[f], w0, a0);     c0 = fmaf(xr1[f], w0, c0);
            a1 = fmaf(xr0[f + 1], w1, a1); c1 = fmaf(xr1[f + 1], w1, c1);
        }
        float acc0 = a0 + a1, acc1 = c0 + c1;
        int r0 = R + rq * 2, r1 = r0 + 1;
        g_h1[(size_t)r0 * F1 + j] = acc0;
        g_h1[(size_t)r1 * F1 + j] = acc1;
        float s1c = __ldg(&ah[h * 16 + o]);
        float s2c = __ldg(&ah[h * 16 + 8 + o]);
        float p10 = acc0 * s1c, p20 = acc0 * s2c;
        float p11 = acc1 * s1c, p21 = acc1 * s2c;
#pragma unroll
        for (int d = 1; d < 8; d <<= 1) {
            p10 += __shfl_xor_sync(0xffffffffu, p10, d);
            p20 += __shfl_xor_sync(0xffffffffu, p20, d);
            p11 += __shfl_xor_sync(0xffffffffu, p11, d);
            p21 += __shfl_xor_sync(0xffffffffu, p21, d);
        }
        if (o == 0) {
            g_s1[r0 * NH + h] = p10; g_s2[r0 * NH + h] = p20;
            g_s1[r1 * NH + h] = p11; g_s2[r1 * NH + h] = p21;
        }
        sred[tid] = acc0 + acc1;
        __syncthreads();
        for (int st = 512; st >= 64; st >>= 1) {
            if (tid < st) sred[tid] += sred[tid + st];
            __syncthreads();
        }
        if (tid < 64) atomicAdd(&g_mean1[b * F1 + tid], sred[tid] * (1.0f / NN));
    }
    gridbar(0);

    // ===== P2: att1 + ELU + GEMM2 + scores + mean2 (blocks 0..127, warp/row) =====
    if (bid < 128) {
        for (int i = tid; i < 1024; i += NT)
            ((float4*)sx)[i] = ((const float4*)Wo)[i];
        __syncthreads();
        float* sWo = sx;                 // 4096 floats
        float* sm2 = sx + 4096;          // 2048 floats

        const int w = tid >> 5, lane = tid & 31;
        const int r = bid * 32 + w;
        const int b = r >> 11, n = r & (NN - 1);
        const int j0 = lane, j1 = lane + 32;
        const int h0 = lane >> 3, h1 = h0 + 4;
        const int st = g_offs[n], deg = g_cnt[n];
        const int*   tg  = g_tgt + st;
        const float* s2p = g_s2 + (size_t)b * NN * NH;
        const float* h1p = g_h1 + (size_t)b * NN * F1;
        float o0, o1;
        if (deg == 0) {
            o0 = g_mean1[b * F1 + j0] + __ldg(&bh[j0]);
            o1 = g_mean1[b * F1 + j1] + __ldg(&bh[j1]);
        } else if (deg <= MAXD) {
            // stage edge list in per-warp smem (coalesced)
            if (lane < deg)       stg[w][lane]      = tg[lane];
            if (lane + 32 < deg)  stg[w][lane + 32] = tg[lane + 32];
            __syncwarp();
            float s1v0 = g_s1[(b * NN + n) * NH + h0];
            float s1v1 = g_s1[(b * NN + n) * NH + h1];
            float m0 = -1e30f, m1 = -1e30f;
            for (int k = 0; k < deg; k += 4) {
#pragma unroll
                for (int q = 0; q < 4; q++) {
                    int kk = k + q;
                    int t  = stg[w][kk < deg ? kk : 0];
                    float e0 = lrelu(s1v0 + s2p[t * NH + h0]);
                    float e1 = lrelu(s1v1 + s2p[t * NH + h1]);
                    if (kk < deg) { m0 = fmaxf(m0, e0); m1 = fmaxf(m1, e1); }
                }
            }
            float den0 = 0.f, den1 = 0.f, acc0 = 0.f, acc1 = 0.f;
            for (int k = 0; k < deg; k += 4) {
#pragma unroll
                for (int q = 0; q < 4; q++) {
                    int kk = k + q;
                    int t  = stg[w][kk < deg ? kk : 0];
                    float e0 = lrelu(s1v0 + s2p[t * NH + h0]);
                    float e1 = lrelu(s1v1 + s2p[t * NH + h1]);
                    float ha = h1p[t * F1 + j0];
                    float hb = h1p[t * F1 + j1];
                    e0 = (kk < deg) ? e0 : -1e30f;
                    e1 = (kk < deg) ? e1 : -1e30f;
                    float w0 = __expf(e0 - m0);
                    float w1 = __expf(e1 - m1);
                    den0 += w0; den1 += w1;
                    acc0 = fmaf(w0, ha, acc0);
                    acc1 = fmaf(w1, hb, acc1);
                }
            }
            o0 = acc0 / den0 + __ldg(&bh[j0]);
            o1 = acc1 / den1 + __ldg(&bh[j1]);
        } else {
            // fallback (deg > MAXD): original gmem loop
            float s1v0 = g_s1[(b * NN + n) * NH + h0];
            float s1v1 = g_s1[(b * NN + n) * NH + h1];
            float m0 = -1e30f, m1 = -1e30f;
            for (int k = 0; k < deg; k++) {
                int t = tg[k];
                m0 = fmaxf(m0, lrelu(s1v0 + s2p[t * NH + h0]));
                m1 = fmaxf(m1, lrelu(s1v1 + s2p[t * NH + h1]));
            }
            float den0 = 0.f, den1 = 0.f, acc0 = 0.f, acc1 = 0.f;
            for (int k = 0; k < deg; k++) {
                int t = tg[k];
                float w0 = __expf(lrelu(s1v0 + s2p[t * NH + h0]) - m0);
                float w1 = __expf(lrelu(s1v1 + s2p[t * NH + h1]) - m1);
                den0 += w0; den1 += w1;
                acc0 = fmaf(w0, h1p[t * F1 + j0], acc0);
                acc1 = fmaf(w1, h1p[t * F1 + j1], acc1);
            }
            o0 = acc0 / den0 + __ldg(&bh[j0]);
            o1 = acc1 / den1 + __ldg(&bh[j1]);
        }
        float x1a = (o0 > 0.f) ? o0 : (__expf(o0) - 1.0f);
        float x1b = (o1 > 0.f) ? o1 : (__expf(o1) - 1.0f);

        // GEMM2 via warp shuffles
        float g0 = 0.f, g1 = 0.f;
#pragma unroll
        for (int f = 0; f < 32; f++) {
            float xf = __shfl_sync(0xffffffffu, x1a, f);
            g0 = fmaf(xf, sWo[f * FOUT + j0], g0);
            g1 = fmaf(xf, sWo[f * FOUT + j1], g1);
        }
#pragma unroll
        for (int f = 0; f < 32; f++) {
            float xf = __shfl_sync(0xffffffffu, x1b, f);
            g0 = fmaf(xf, sWo[(f + 32) * FOUT + j0], g0);
            g1 = fmaf(xf, sWo[(f + 32) * FOUT + j1], g1);
        }
        g_h2[(size_t)r * FOUT + j0] = g0;
        g_h2[(size_t)r * FOUT + j1] = g1;
        float p1 = fmaf(g0, __ldg(&ao[j0]), g1 * __ldg(&ao[j1]));
        float p2 = fmaf(g0, __ldg(&ao[FOUT + j0]), g1 * __ldg(&ao[FOUT + j1]));
#pragma unroll
        for (int d = 16; d >= 1; d >>= 1) {
            p1 += __shfl_xor_sync(0xffffffffu, p1, d);
            p2 += __shfl_xor_sync(0xffffffffu, p2, d);
        }
        if (lane == 0) { g_t1[r] = p1; g_t2[r] = p2; }

        sm2[w * 64 + j0] = g0;
        sm2[w * 64 + j1] = g1;
        __syncthreads();
        for (int s = 16; s > 0; s >>= 1) {
            if (w < s) {
                sm2[w * 64 + j0] += sm2[(w + s) * 64 + j0];
                sm2[w * 64 + j1] += sm2[(w + s) * 64 + j1];
            }
            __syncthreads();
        }
        if (tid < 64) atomicAdd(&g_mean2[(bid >> 6) * FOUT + tid], sm2[tid] * (1.0f / NN));
    }
    gridbar(1);

    // ===== P3: att2 -> out (warp-per-row, staged edges, 8-wide) =====
    {
        const int w = tid >> 5, lane = tid & 31;
        const int r = w * NB + bid;
        if (r < BB * NN) {
            const int b = r >> 11, n = r & (NN - 1);
            const int st = g_offs[n], deg = g_cnt[n];
            const int*   tg  = g_tgt + st;
            const float* t2p = g_t2 + (size_t)b * NN;
            const float* h2p = g_h2 + (size_t)b * NN * FOUT;
            float o0, o1;
            if (deg == 0) {
                o0 = g_mean2[b * FOUT + lane]      + __ldg(&bo[lane]);
                o1 = g_mean2[b * FOUT + lane + 32] + __ldg(&bo[lane + 32]);
            } else if (deg <= MAXD) {
                if (lane < deg)       stg[w][lane]      = tg[lane];
                if (lane + 32 < deg)  stg[w][lane + 32] = tg[lane + 32];
                __syncwarp();
                float s1v = g_t1[b * NN + n];
                float m = -1e30f;
                for (int k = 0; k < deg; k += 8) {
#pragma unroll
                    for (int q = 0; q < 8; q++) {
                        int kk = k + q;
                        int t  = stg[w][kk < deg ? kk : 0];
                        float e = lrelu(s1v + t2p[t]);
                        if (kk < deg) m = fmaxf(m, e);
                    }
                }
                float den = 0.f, a0 = 0.f, a1 = 0.f;
                for (int k = 0; k < deg; k += 4) {
#pragma unroll
                    for (int q = 0; q < 4; q++) {
                        int kk = k + q;
                        int t  = stg[w][kk < deg ? kk : 0];
                        float e = lrelu(s1v + t2p[t]);
                        float h0 = h2p[t * FOUT + lane];
                        float h1 = h2p[t * FOUT + lane + 32];
                        e = (kk < deg) ? e : -1e30f;
                        float wt = __expf(e - m);
                        den += wt;
                        a0 = fmaf(wt, h0, a0);
                        a1 = fmaf(wt, h1, a1);
                    }
                }
                o0 = a0 / den + __ldg(&bo[lane]);
                o1 = a1 / den + __ldg(&bo[lane + 32]);
            } else {
                float s1v = g_t1[b * NN + n];
                float m = -1e30f;
                for (int k = 0; k < deg; k++)
                    m = fmaxf(m, lrelu(s1v + t2p[tg[k]]));
                float den = 0.f, a0 = 0.f, a1 = 0.f;
                for (int k = 0; k < deg; k++) {
                    int t = tg[k];
                    float wt = __expf(lrelu(s1v + t2p[t]) - m);
                    den += wt;
                    a0 = fmaf(wt, h2p[t * FOUT + lane], a0);
                    a1 = fmaf(wt, h2p[t * FOUT + lane + 32], a1);
                }
                o0 = a0 / den + __ldg(&bo[lane]);
                o1 = a1 / den + __ldg(&bo[lane + 32]);
            }
            out[(size_t)r * FOUT + lane]      = o0;
            out[(size_t)r * FOUT + lane + 32] = o1;
        }
    }
    gridbar(2);

    // ===== P4: log_softmax per (b,o) column (blocks 0..127) || cleanup =====
    if (bid < 128) {
        int b = bid >> 6, o = bid & 63;
        const int w = tid >> 5, lane = tid & 31;
        const float* base = out + (size_t)b * NN * FOUT + o;
        float v0 = base[(size_t)tid * FOUT];
        float v1 = base[(size_t)(tid + NT) * FOUT];
        // max: warp shuffle + one smem stage
        float m = fmaxf(v0, v1);
#pragma unroll
        for (int d = 16; d >= 1; d >>= 1)
            m = fmaxf(m, __shfl_xor_sync(0xffffffffu, m, d));
        if (lane == 0) sred[w] = m;
        __syncthreads();
        if (tid < 32) {
            float mw = sred[tid];
#pragma unroll
            for (int d = 16; d >= 1; d >>= 1)
                mw = fmaxf(mw, __shfl_xor_sync(0xffffffffu, mw, d));
            if (tid == 0) sred[0] = mw;
        }
        __syncthreads();
        float mm = sred[0];
        __syncthreads();
        float s = __expf(v0 - mm) + __expf(v1 - mm);
#pragma unroll
        for (int d = 16; d >= 1; d >>= 1)
            s += __shfl_xor_sync(0xffffffffu, s, d);
        if (lane == 0) sred[w] = s;
        __syncthreads();
        if (tid < 32) {
            float sw = sred[tid];
#pragma unroll
            for (int d = 16; d >= 1; d >>= 1)
                sw += __shfl_xor_sync(0xffffffffu, sw, d);
            if (tid == 0) sred[0] = sw;
        }
        __syncthreads();
        float lse = mm + __logf(sred[0]);
        float* basew = out + (size_t)b * NN * FOUT + o;
        basew[(size_t)tid * FOUT]        = v0 - lse;
        basew[(size_t)(tid + NT) * FOUT] = v1 - lse;
    } else {
        int cb = bid - 128;   // 0..19
        for (int i = cb * NT + tid; i < EE; i += 20 * NT) {
            int s = edges[i], t = edges[EE + i];
            unsigned bit = (unsigned)s * NN + (unsigned)t;
            atomicAnd(&g_bm[bit >> 5], ~(1u << (bit & 31u)));
        }
        if (cb == 0) {
            if (tid < BB * F1)                  g_mean1[tid] = 0.f;
            else if (tid < BB * (F1 + FOUT))    g_mean2[tid - BB * F1] = 0.f;
        }
    }
}

// ---------------- launch -------------------------------------------------------
extern "C" void kernel_launch(void* const* d_in, const int* in_sizes, int n_in,
                              void* d_out, int out_size) {
    const float* x     = (const float*)d_in[0];
    const int*   edges = (const int*)  d_in[1];
    const float* Wh    = (const float*)d_in[2];
    const float* ah    = (const float*)d_in[3];
    const float* bh    = (const float*)d_in[4];
    const float* Wo    = (const float*)d_in[5];
    const float* ao    = (const float*)d_in[6];
    const float* bo    = (const float*)d_in[7];
    float* out = (float*)d_out;

    mega<<<NB, NT>>>(x, edges, Wh, ah, bh, Wo, ao, bo, out);
}